// round 12
// baseline (speedup 1.0000x reference)
#include <cuda_runtime.h>
#include <math.h>

#define G3 32768
#define NVIEW 8

typedef unsigned long long ull;

// ---- all hot weights in constant memory (48.6 KB < 64 KB cbank) ----
__constant__ float c_rw1[16 * 4];
__constant__ float c_rb1[16];
__constant__ float c_rw2[32 * 16];
__constant__ float c_rb2[32];
__constant__ float c_bw1[64 * 96];
__constant__ float c_bb1[64];
__constant__ float c_bw2[32 * 64];
__constant__ float c_bb2[32];
__constant__ float c_vw1[32 * 32];
__constant__ float c_vb1[32];
__constant__ float c_vw2[33 * 32];
__constant__ float c_vb2[33];
__constant__ float c_v2w1[32 * 32];
__constant__ float c_v2b1[32];
__constant__ float c_v2w2[32];
__constant__ float c_v2b2[1];

__device__ __forceinline__ float elu_f(float x)  { return x > 0.f ? x : (__expf(x) - 1.f); }
__device__ __forceinline__ float sigm_f(float x) { return 1.f / (1.f + __expf(-x)); }

__device__ __forceinline__ ull pk2(float lo, float hi) {
    ull r; asm("mov.b64 %0, {%1, %2};" : "=l"(r) : "f"(lo), "f"(hi)); return r;
}
__device__ __forceinline__ float2 upk2(ull a) {
    float lo, hi; asm("mov.b64 {%0, %1}, %2;" : "=f"(lo), "=f"(hi) : "l"(a));
    return make_float2(lo, hi);
}
__device__ __forceinline__ ull fma2(ull a, ull b, ull c) {
    ull d; asm("fma.rn.f32x2 %0, %1, %2, %3;" : "=l"(d) : "l"(a), "l"(b), "l"(c)); return d;
}
__device__ __forceinline__ ull mul2(ull a, ull b) {
    ull d; asm("mul.rn.f32x2 %0, %1, %2;" : "=l"(d) : "l"(a), "l"(b)); return d;
}
__device__ __forceinline__ ull add2(ull a, ull b) {
    ull d; asm("add.rn.f32x2 %0, %1, %2;" : "=l"(d) : "l"(a), "l"(b)); return d;
}
__device__ __forceinline__ float hsum2(ull a) { float2 f = upk2(a); return f.x + f.y; }

// Packed dot over NP f32x2 pairs. wr points into a __constant__ array at a
// 16B-aligned offset; after inlining the loads lower to constant-space loads
// (uniform port), leaving the L1/shared crossbar free.
template<int NP>
__device__ __forceinline__ float pdot(const float* __restrict__ wr, const ull* __restrict__ xp) {
    ull a0 = 0ull, a1 = 0ull;
    #pragma unroll
    for (int k = 0; k < NP / 2; ++k) {
        const ulonglong2 w = *reinterpret_cast<const ulonglong2*>(wr + 4 * k);
        a0 = fma2(w.x, xp[2 * k], a0);
        a1 = fma2(w.y, xp[2 * k + 1], a1);
    }
    return hsum2(add2(a0, a1));
}

__global__ __launch_bounds__(128)
void ibr_agg_v7_kernel(
    const float* __restrict__ features,   // (B,N,32,G3)
    const float* __restrict__ mask,       // (B,N,1,G3)
    const float* __restrict__ depth,      // (B,N,1,G3)
    const float* __restrict__ vdir,       // (B,N,3,G3)
    const float* __restrict__ g_sw,  const float* __restrict__ g_sb,    // (32,65),(32)
    float* __restrict__ out)              // (B,32,G3)
{
    // only the stat head stays in shared (once per voxel; 65-wide rows unaligned for cbank f4)
    __shared__ __align__(16) float s_sw[32 * 68];
    __shared__ __align__(16) float s_sb[32];

    const int tid = threadIdx.x;
    for (int i = tid; i < 32 * 65; i += 128) { int o = i / 65, c = i % 65; s_sw[o * 68 + c] = g_sw[i]; }
    if (tid < 32) s_sb[tid] = g_sb[tid];
    __syncthreads();

    const float EPS  = 1e-8f;
    const float v2b2 = c_v2b2[0];

    const int gv = blockIdx.x * 128 + tid;   // [0, 65536): (b, voxel)
    const int b  = gv >> 15;
    const int v  = gv & (G3 - 1);

    // ---- mask sum ----
    float msum = 0.f;
    #pragma unroll
    for (int n = 0; n < NVIEW; ++n) msum += __ldg(&mask[(b * NVIEW + n) * G3 + v]);
    const float minv = 1.f / (msum + EPS);
    const float ws   = msum * minv;

    // ================= phase 1: packed A1=Sum(w f), A2=Sum(w f^2) =================
    float fsave[NVIEW][32];            // per-thread local cache of feats
    ull A1p[16], A2p[16];
    #pragma unroll
    for (int j = 0; j < 16; ++j) { A1p[j] = 0ull; A2p[j] = 0ull; }

    #pragma unroll 1
    for (int n = 0; n < NVIEW; ++n) {
        const int bn = b * NVIEW + n;
        const float i0 = __ldg(&vdir[(bn * 3 + 0) * G3 + v]);
        const float i1 = __ldg(&vdir[(bn * 3 + 1) * G3 + v]);
        const float i2 = __ldg(&vdir[(bn * 3 + 2) * G3 + v]);
        const float i3 = __ldg(&depth[bn * G3 + v]);
        const float wn = __ldg(&mask[bn * G3 + v]) * minv;
        const ull  wn2 = pk2(wn, wn);

        ull hp8[8];
        #pragma unroll
        for (int o = 0; o < 16; o += 2) {
            const float4 wa = *reinterpret_cast<const float4*>(&c_rw1[o * 4]);
            const float4 wb = *reinterpret_cast<const float4*>(&c_rw1[(o + 1) * 4]);
            const float ha = elu_f(c_rb1[o]     + wa.x * i0 + wa.y * i1 + wa.z * i2 + wa.w * i3);
            const float hb = elu_f(c_rb1[o + 1] + wb.x * i0 + wb.y * i1 + wb.z * i2 + wb.w * i3);
            hp8[o >> 1] = pk2(ha, hb);
        }

        const float* fbase = &features[(bn * 32) * G3 + v];
        #pragma unroll
        for (int j = 0; j < 16; ++j) {
            const float a = __ldg(&fbase[(2 * j) * G3])
                          + elu_f(c_rb2[2 * j] + pdot<8>(&c_rw2[(2 * j) * 16], hp8));
            const float c = __ldg(&fbase[(2 * j + 1) * G3])
                          + elu_f(c_rb2[2 * j + 1] + pdot<8>(&c_rw2[(2 * j + 1) * 16], hp8));
            fsave[n][2 * j]     = a;
            fsave[n][2 * j + 1] = c;
            const ull fp = pk2(a, c);
            A1p[j] = fma2(wn2, fp, A1p[j]);
            A2p[j] = fma2(wn2, mul2(fp, fp), A2p[j]);
        }
    }

    // mean/var packed: var = A2 - mean^2 (2 - ws)
    {
        const float nw = -(2.f - ws);
        const ull  nw2 = pk2(nw, nw);
        #pragma unroll
        for (int j = 0; j < 16; ++j) {
            const ull m = A1p[j];
            A2p[j] = fma2(mul2(m, m), nw2, A2p[j]);   // A1p = mean, A2p = var
        }
    }

    // ---- hbase[o] = bb1[o] + bw1[o,0:32].mean + bw1[o,32:64].var (local) ----
    float hbase[64];
    #pragma unroll 1
    for (int o = 0; o < 64; ++o) {
        const float* rm = &c_bw1[o * 96];
        hbase[o] = c_bb1[o] + pdot<16>(rm, A1p) + pdot<16>(rm + 32, A2p);
    }

    // ================= phase 2: per-view MLPs; S, Up, Vvp =================
    ull Up[16], Vvp[16];
    float S = 0.f;
    #pragma unroll
    for (int j = 0; j < 16; ++j) { Up[j] = 0ull; Vvp[j] = 0ull; }

    #pragma unroll 1
    for (int n = 0; n < NVIEW; ++n) {
        const int bn = b * NVIEW + n;
        const float mval = __ldg(&mask[bn * G3 + v]);
        const float wn   = mval * minv;

        ull fp[16];
        #pragma unroll
        for (int j = 0; j < 16; ++j) fp[j] = pk2(fsave[n][2 * j], fsave[n][2 * j + 1]);

        // --- base: h = elu(hbase + bw1[:,64:96].f) (64); xx = elu(bb2 + bw2.h) (32) ---
        float xx[32];
        #pragma unroll
        for (int j = 0; j < 32; ++j) xx[j] = c_bb2[j];

        #pragma unroll 1
        for (int oc = 0; oc < 4; ++oc) {
            const int o16 = oc * 16;
            ull hp[8];
            #pragma unroll
            for (int k = 0; k < 16; k += 2) {
                const float ha = elu_f(hbase[o16 + k]     + pdot<16>(&c_bw1[(o16 + k) * 96 + 64], fp));
                const float hb = elu_f(hbase[o16 + k + 1] + pdot<16>(&c_bw1[(o16 + k + 1) * 96 + 64], fp));
                hp[k >> 1] = pk2(ha, hb);
            }
            #pragma unroll
            for (int j = 0; j < 32; ++j)
                xx[j] += pdot<8>(&c_bw2[j * 64 + o16], hp);
        }
        ull xxp[16];
        #pragma unroll
        for (int j = 0; j < 16; ++j)
            xxp[j] = pk2(elu_f(xx[2 * j]), elu_f(xx[2 * j + 1]));

        // --- vis: t = xx*wn ; hv = elu(vw1.t) ; xx += elu(vb2 + vw2.hv) ; va ---
        const ull wn2 = pk2(wn, wn);
        ull tp[16];
        #pragma unroll
        for (int j = 0; j < 16; ++j) tp[j] = mul2(xxp[j], wn2);

        ull hvp[16];
        #pragma unroll
        for (int o = 0; o < 32; o += 2) {
            const float a = elu_f(c_vb1[o]     + pdot<16>(&c_vw1[o * 32], tp));
            const float c = elu_f(c_vb1[o + 1] + pdot<16>(&c_vw1[(o + 1) * 32], tp));
            hvp[o >> 1] = pk2(a, c);
        }
        #pragma unroll
        for (int j = 0; j < 32; j += 2) {
            const float a = elu_f(c_vb2[j]     + pdot<16>(&c_vw2[j * 32], hvp));
            const float c = elu_f(c_vb2[j + 1] + pdot<16>(&c_vw2[(j + 1) * 32], hvp));
            xxp[j >> 1] = add2(xxp[j >> 1], pk2(a, c));       // x = x + x_res
        }
        const float va  = c_vb2[32] + pdot<16>(&c_vw2[32 * 32], hvp);
        const float vis = sigm_f(elu_f(va)) * mval;

        // --- vis2: t2 = xx*vis ; s2 = v2b2 + v2w2.elu(v2w1.t2) ---
        const ull visd = pk2(vis, vis);
        #pragma unroll
        for (int j = 0; j < 16; ++j) tp[j] = mul2(xxp[j], visd);

        float s2 = v2b2;
        #pragma unroll
        for (int o = 0; o < 32; o += 2) {
            const float a = elu_f(c_v2b1[o]     + pdot<16>(&c_v2w1[o * 32], tp));
            const float c = elu_f(c_v2b1[o + 1] + pdot<16>(&c_v2w1[(o + 1) * 32], tp));
            s2 += c_v2w2[o] * a + c_v2w2[o + 1] * c;
        }
        const float vis2 = sigm_f(s2) * mval;

        S += vis2;
        const ull v2d = pk2(vis2, vis2);
        #pragma unroll
        for (int j = 0; j < 16; ++j) {
            Up[j]  = fma2(v2d, xxp[j], Up[j]);
            Vvp[j] = fma2(v2d, mul2(xxp[j], xxp[j]), Vvp[j]);
        }
    }

    // ================= second mean/var + stat head (packed) =================
    const float Sinv  = 1.f / (S + EPS);
    const float w2s   = S * Sinv;
    const float wmean = w2s * 0.125f;
    {
        const ull sd  = pk2(Sinv, Sinv);
        const float nw = -(2.f - w2s);
        const ull nw2 = pk2(nw, nw);
        #pragma unroll
        for (int j = 0; j < 16; ++j) {
            const ull m2 = mul2(Up[j], sd);
            Up[j]  = m2;                                        // mean2
            Vvp[j] = fma2(mul2(m2, m2), nw2, mul2(Vvp[j], sd)); // var2
        }
    }

    #pragma unroll 1
    for (int o = 0; o < 32; ++o) {
        const float* wr = &s_sw[o * 68];
        const float acc = s_sb[o] + pdot<16>(wr, Up) + pdot<16>(wr + 32, Vvp) + wr[64] * wmean;
        out[(b * 32 + o) * G3 + v] = elu_f(acc);
    }
}

extern "C" void kernel_launch(void* const* d_in, const int* in_sizes, int n_in,
                              void* d_out, int out_size) {
    (void)in_sizes; (void)n_in; (void)out_size;
    const float* features = (const float*)d_in[0];
    const float* mask     = (const float*)d_in[1];
    const float* depth    = (const float*)d_in[2];
    const float* vdir     = (const float*)d_in[3];

    // Populate constant bank (async D2D copies: graph-capturable, no allocation)
    cudaMemcpyToSymbolAsync(c_rw1,  d_in[4],  16 * 4  * 4, 0, cudaMemcpyDeviceToDevice);
    cudaMemcpyToSymbolAsync(c_rb1,  d_in[5],  16      * 4, 0, cudaMemcpyDeviceToDevice);
    cudaMemcpyToSymbolAsync(c_rw2,  d_in[6],  32 * 16 * 4, 0, cudaMemcpyDeviceToDevice);
    cudaMemcpyToSymbolAsync(c_rb2,  d_in[7],  32      * 4, 0, cudaMemcpyDeviceToDevice);
    cudaMemcpyToSymbolAsync(c_bw1,  d_in[8],  64 * 96 * 4, 0, cudaMemcpyDeviceToDevice);
    cudaMemcpyToSymbolAsync(c_bb1,  d_in[9],  64      * 4, 0, cudaMemcpyDeviceToDevice);
    cudaMemcpyToSymbolAsync(c_bw2,  d_in[10], 32 * 64 * 4, 0, cudaMemcpyDeviceToDevice);
    cudaMemcpyToSymbolAsync(c_bb2,  d_in[11], 32      * 4, 0, cudaMemcpyDeviceToDevice);
    cudaMemcpyToSymbolAsync(c_vw1,  d_in[12], 32 * 32 * 4, 0, cudaMemcpyDeviceToDevice);
    cudaMemcpyToSymbolAsync(c_vb1,  d_in[13], 32      * 4, 0, cudaMemcpyDeviceToDevice);
    cudaMemcpyToSymbolAsync(c_vw2,  d_in[14], 33 * 32 * 4, 0, cudaMemcpyDeviceToDevice);
    cudaMemcpyToSymbolAsync(c_vb2,  d_in[15], 33      * 4, 0, cudaMemcpyDeviceToDevice);
    cudaMemcpyToSymbolAsync(c_v2w1, d_in[16], 32 * 32 * 4, 0, cudaMemcpyDeviceToDevice);
    cudaMemcpyToSymbolAsync(c_v2b1, d_in[17], 32      * 4, 0, cudaMemcpyDeviceToDevice);
    cudaMemcpyToSymbolAsync(c_v2w2, d_in[18], 32      * 4, 0, cudaMemcpyDeviceToDevice);
    cudaMemcpyToSymbolAsync(c_v2b2, d_in[19], 1       * 4, 0, cudaMemcpyDeviceToDevice);

    const float* stat_w = (const float*)d_in[20];
    const float* stat_b = (const float*)d_in[21];
    float* out = (float*)d_out;

    ibr_agg_v7_kernel<<<512, 128>>>(features, mask, depth, vdir, stat_w, stat_b, out);
}

// round 13
// speedup vs baseline: 1.2141x; 1.2141x over previous
#include <cuda_runtime.h>
#include <math.h>

#define G3 32768
#define NVIEW 8

typedef unsigned long long ull;

// ---- dynamic shared layout (float offsets), weights + U/V accumulators ----
#define OFF_RW1   0
#define OFF_RB1   64
#define OFF_RW2   80
#define OFF_RB2   592
#define OFF_BW1F  624
#define OFF_BW2   2672
#define OFF_BB2   4720
#define OFF_VW1   4752
#define OFF_VB1   5776
#define OFF_VW2   5808
#define OFF_VB2   6864
#define OFF_V2W1  6900
#define OFF_V2B1  7924
#define OFF_V2W2  7956
#define OFF_SW    7988
#define OFF_SB    10164
#define OFF_ACC   10200                           // ull region (byte 40800)
#define SMEM_BYTES (OFF_ACC * 4 + 32 * 128 * 8)   // 40800 + 32768 = 73568

__device__ __forceinline__ float elu_f(float x)  { return x > 0.f ? x : (__expf(x) - 1.f); }
__device__ __forceinline__ float sigm_f(float x) { return 1.f / (1.f + __expf(-x)); }

__device__ __forceinline__ ull pk2(float lo, float hi) {
    ull r; asm("mov.b64 %0, {%1, %2};" : "=l"(r) : "f"(lo), "f"(hi)); return r;
}
__device__ __forceinline__ float2 upk2(ull a) {
    float lo, hi; asm("mov.b64 {%0, %1}, %2;" : "=f"(lo), "=f"(hi) : "l"(a));
    return make_float2(lo, hi);
}
__device__ __forceinline__ ull fma2(ull a, ull b, ull c) {
    ull d; asm("fma.rn.f32x2 %0, %1, %2, %3;" : "=l"(d) : "l"(a), "l"(b), "l"(c)); return d;
}
__device__ __forceinline__ ull mul2(ull a, ull b) {
    ull d; asm("mul.rn.f32x2 %0, %1, %2;" : "=l"(d) : "l"(a), "l"(b)); return d;
}
__device__ __forceinline__ ull add2(ull a, ull b) {
    ull d; asm("add.rn.f32x2 %0, %1, %2;" : "=l"(d) : "l"(a), "l"(b)); return d;
}
__device__ __forceinline__ float hsum2(ull a) { float2 f = upk2(a); return f.x + f.y; }

// Single packed dot (used in per-voxel sections)
template<int NP>
__device__ __forceinline__ float pdot(const float* __restrict__ wr, const ull* __restrict__ xp) {
    ull a0 = 0ull, a1 = 0ull;
    #pragma unroll
    for (int k = 0; k < NP / 2; ++k) {
        const ulonglong2 w = *reinterpret_cast<const ulonglong2*>(wr + 4 * k);
        a0 = fma2(w.x, xp[2 * k], a0);
        a1 = fma2(w.y, xp[2 * k + 1], a1);
    }
    return hsum2(add2(a0, a1));
}

// Paired packed dot: one weight load feeds BOTH views (4 fma2 per LDS.128).
template<int NP>
__device__ __forceinline__ void pdot2(const float* __restrict__ wr,
                                      const ull* __restrict__ xa, const ull* __restrict__ xb,
                                      float& ra, float& rb) {
    ull a0 = 0ull, a1 = 0ull, b0 = 0ull, b1 = 0ull;
    #pragma unroll
    for (int k = 0; k < NP / 2; ++k) {
        const ulonglong2 w = *reinterpret_cast<const ulonglong2*>(wr + 4 * k);
        a0 = fma2(w.x, xa[2 * k], a0);
        b0 = fma2(w.x, xb[2 * k], b0);
        a1 = fma2(w.y, xa[2 * k + 1], a1);
        b1 = fma2(w.y, xb[2 * k + 1], b1);
    }
    ra = hsum2(add2(a0, a1));
    rb = hsum2(add2(b0, b1));
}

__global__ __launch_bounds__(128)
void ibr_agg_v8_kernel(
    const float* __restrict__ features,   // (B,N,32,G3)
    const float* __restrict__ mask,       // (B,N,1,G3)
    const float* __restrict__ depth,      // (B,N,1,G3)
    const float* __restrict__ vdir,       // (B,N,3,G3)
    const float* __restrict__ g_rw1, const float* __restrict__ g_rb1,
    const float* __restrict__ g_rw2, const float* __restrict__ g_rb2,
    const float* __restrict__ g_bw1, const float* __restrict__ g_bb1,
    const float* __restrict__ g_bw2, const float* __restrict__ g_bb2,
    const float* __restrict__ g_vw1, const float* __restrict__ g_vb1,
    const float* __restrict__ g_vw2, const float* __restrict__ g_vb2,
    const float* __restrict__ g_v2w1, const float* __restrict__ g_v2b1,
    const float* __restrict__ g_v2w2, const float* __restrict__ g_v2b2,
    const float* __restrict__ g_sw,  const float* __restrict__ g_sb,
    float* __restrict__ out)              // (B,32,G3)
{
    extern __shared__ __align__(16) float S[];
    float* s_rw1  = S + OFF_RW1;
    float* s_rb1  = S + OFF_RB1;
    float* s_rw2  = S + OFF_RW2;
    float* s_rb2  = S + OFF_RB2;
    float* s_bw1f = S + OFF_BW1F;
    float* s_bw2  = S + OFF_BW2;
    float* s_bb2  = S + OFF_BB2;
    float* s_vw1  = S + OFF_VW1;
    float* s_vb1  = S + OFF_VB1;
    float* s_vw2  = S + OFF_VW2;
    float* s_vb2  = S + OFF_VB2;
    float* s_v2w1 = S + OFF_V2W1;
    float* s_v2b1 = S + OFF_V2B1;
    float* s_v2w2 = S + OFF_V2W2;
    float* s_sw   = S + OFF_SW;
    float* s_sb   = S + OFF_SB;
    ull*   s_acc  = reinterpret_cast<ull*>(S + OFF_ACC);   // [32][128]: U at j, V at 16+j

    const int tid = threadIdx.x;

    for (int i = tid; i < 16 * 4;  i += 128) s_rw1[i] = g_rw1[i];
    if (tid < 16) s_rb1[tid] = g_rb1[tid];
    for (int i = tid; i < 32 * 16; i += 128) s_rw2[i] = g_rw2[i];
    if (tid < 32) s_rb2[tid] = g_rb2[tid];
    for (int i = tid; i < 64 * 32; i += 128) { int o = i >> 5, c = i & 31; s_bw1f[i] = g_bw1[o * 96 + 64 + c]; }
    for (int i = tid; i < 32 * 64; i += 128) s_bw2[i] = g_bw2[i];
    if (tid < 32) s_bb2[tid] = g_bb2[tid];
    for (int i = tid; i < 32 * 32; i += 128) s_vw1[i] = g_vw1[i];
    if (tid < 32) s_vb1[tid] = g_vb1[tid];
    for (int i = tid; i < 33 * 32; i += 128) s_vw2[i] = g_vw2[i];
    if (tid < 33) s_vb2[tid] = g_vb2[tid];
    for (int i = tid; i < 32 * 32; i += 128) s_v2w1[i] = g_v2w1[i];
    if (tid < 32) s_v2b1[tid] = g_v2b1[tid];
    if (tid < 32) s_v2w2[tid] = g_v2w2[tid];
    for (int i = tid; i < 32 * 65; i += 128) { int o = i / 65, c = i % 65; s_sw[o * 68 + c] = g_sw[i]; }
    if (tid < 32) s_sb[tid] = g_sb[tid];
    #pragma unroll
    for (int j = 0; j < 32; ++j) s_acc[j * 128 + tid] = 0ull;
    __syncthreads();

    const float EPS  = 1e-8f;
    const float v2b2 = __ldg(g_v2b2);

    const int gv = blockIdx.x * 128 + tid;   // [0, 65536): (b, voxel)
    const int b  = gv >> 15;
    const int v  = gv & (G3 - 1);

    // ---- mask sum ----
    float msum = 0.f;
    #pragma unroll
    for (int n = 0; n < NVIEW; ++n) msum += __ldg(&mask[(b * NVIEW + n) * G3 + v]);
    const float minv = 1.f / (msum + EPS);
    const float ws   = msum * minv;

    // ================= phase 1 (view pairs): A1=Sum(w f), A2=Sum(w f^2) =================
    float fsave[NVIEW][32];
    ull A1p[16], A2p[16];
    #pragma unroll
    for (int j = 0; j < 16; ++j) { A1p[j] = 0ull; A2p[j] = 0ull; }

    #pragma unroll 1
    for (int np = 0; np < NVIEW / 2; ++np) {
        const int bnA = b * NVIEW + 2 * np;
        const int bnB = bnA + 1;
        const float iA0 = __ldg(&vdir[(bnA * 3 + 0) * G3 + v]);
        const float iA1 = __ldg(&vdir[(bnA * 3 + 1) * G3 + v]);
        const float iA2 = __ldg(&vdir[(bnA * 3 + 2) * G3 + v]);
        const float iA3 = __ldg(&depth[bnA * G3 + v]);
        const float iB0 = __ldg(&vdir[(bnB * 3 + 0) * G3 + v]);
        const float iB1 = __ldg(&vdir[(bnB * 3 + 1) * G3 + v]);
        const float iB2 = __ldg(&vdir[(bnB * 3 + 2) * G3 + v]);
        const float iB3 = __ldg(&depth[bnB * G3 + v]);
        const float wnA = __ldg(&mask[bnA * G3 + v]) * minv;
        const float wnB = __ldg(&mask[bnB * G3 + v]) * minv;
        const ull wn2A = pk2(wnA, wnA), wn2B = pk2(wnB, wnB);

        ull hp8A[8], hp8B[8];
        #pragma unroll
        for (int o = 0; o < 16; o += 2) {
            const float4 wa = *reinterpret_cast<const float4*>(&s_rw1[o * 4]);
            const float4 wb = *reinterpret_cast<const float4*>(&s_rw1[(o + 1) * 4]);
            const float b0 = s_rb1[o], b1 = s_rb1[o + 1];
            hp8A[o >> 1] = pk2(elu_f(b0 + wa.x * iA0 + wa.y * iA1 + wa.z * iA2 + wa.w * iA3),
                               elu_f(b1 + wb.x * iA0 + wb.y * iA1 + wb.z * iA2 + wb.w * iA3));
            hp8B[o >> 1] = pk2(elu_f(b0 + wa.x * iB0 + wa.y * iB1 + wa.z * iB2 + wa.w * iB3),
                               elu_f(b1 + wb.x * iB0 + wb.y * iB1 + wb.z * iB2 + wb.w * iB3));
        }

        const float* fbA = &features[(bnA * 32) * G3 + v];
        const float* fbB = &features[(bnB * 32) * G3 + v];
        #pragma unroll
        for (int j = 0; j < 16; ++j) {
            float p0A, p0B, p1A, p1B;
            pdot2<8>(&s_rw2[(2 * j) * 16],     hp8A, hp8B, p0A, p0B);
            pdot2<8>(&s_rw2[(2 * j + 1) * 16], hp8A, hp8B, p1A, p1B);
            const float aA = __ldg(&fbA[(2 * j) * G3])     + elu_f(s_rb2[2 * j] + p0A);
            const float cA = __ldg(&fbA[(2 * j + 1) * G3]) + elu_f(s_rb2[2 * j + 1] + p1A);
            const float aB = __ldg(&fbB[(2 * j) * G3])     + elu_f(s_rb2[2 * j] + p0B);
            const float cB = __ldg(&fbB[(2 * j + 1) * G3]) + elu_f(s_rb2[2 * j + 1] + p1B);
            fsave[2 * np][2 * j]         = aA;
            fsave[2 * np][2 * j + 1]     = cA;
            fsave[2 * np + 1][2 * j]     = aB;
            fsave[2 * np + 1][2 * j + 1] = cB;
            const ull fpA = pk2(aA, cA), fpB = pk2(aB, cB);
            A1p[j] = fma2(wn2A, fpA, A1p[j]);
            A2p[j] = fma2(wn2A, mul2(fpA, fpA), A2p[j]);
            A1p[j] = fma2(wn2B, fpB, A1p[j]);
            A2p[j] = fma2(wn2B, mul2(fpB, fpB), A2p[j]);
        }
    }

    // mean/var: var = A2 - mean^2 (2 - ws)
    {
        const float nw = -(2.f - ws);
        const ull  nw2 = pk2(nw, nw);
        #pragma unroll
        for (int j = 0; j < 16; ++j) {
            const ull m = A1p[j];
            A2p[j] = fma2(mul2(m, m), nw2, A2p[j]);
        }
    }

    // ---- hbase[o] (local) ----
    float hbase[64];
    #pragma unroll 1
    for (int o = 0; o < 64; ++o) {
        const float* rm = &g_bw1[o * 96];
        hbase[o] = __ldg(&g_bb1[o]) + pdot<16>(rm, A1p) + pdot<16>(rm + 32, A2p);
    }

    // ================= phase 2 (view pairs): MLPs; S; U/V in smem =================
    float Ssum = 0.f;

    #pragma unroll 1
    for (int np = 0; np < NVIEW / 2; ++np) {
        const int bnA = b * NVIEW + 2 * np;
        const int bnB = bnA + 1;
        const float mvalA = __ldg(&mask[bnA * G3 + v]);
        const float mvalB = __ldg(&mask[bnB * G3 + v]);
        const float wnA = mvalA * minv, wnB = mvalB * minv;

        ull fpA[16], fpB[16];
        #pragma unroll
        for (int j = 0; j < 16; ++j) {
            fpA[j] = pk2(fsave[2 * np][2 * j],     fsave[2 * np][2 * j + 1]);
            fpB[j] = pk2(fsave[2 * np + 1][2 * j], fsave[2 * np + 1][2 * j + 1]);
        }

        // --- base MLP, 16-wide hidden chunks ---
        float xxA[32], xxB[32];
        #pragma unroll
        for (int j = 0; j < 32; ++j) { xxA[j] = s_bb2[j]; xxB[j] = s_bb2[j]; }

        #pragma unroll 1
        for (int oc = 0; oc < 4; ++oc) {
            const int o16 = oc * 16;
            ull hpA[8], hpB[8];
            #pragma unroll
            for (int k = 0; k < 16; k += 2) {
                float pA, pB, qA, qB;
                pdot2<16>(&s_bw1f[(o16 + k) * 32],     fpA, fpB, pA, pB);
                pdot2<16>(&s_bw1f[(o16 + k + 1) * 32], fpA, fpB, qA, qB);
                hpA[k >> 1] = pk2(elu_f(hbase[o16 + k] + pA), elu_f(hbase[o16 + k + 1] + qA));
                hpB[k >> 1] = pk2(elu_f(hbase[o16 + k] + pB), elu_f(hbase[o16 + k + 1] + qB));
            }
            #pragma unroll
            for (int j = 0; j < 32; ++j) {
                float qa, qb;
                pdot2<8>(&s_bw2[j * 64 + o16], hpA, hpB, qa, qb);
                xxA[j] += qa; xxB[j] += qb;
            }
        }
        ull xxpA[16], xxpB[16];
        #pragma unroll
        for (int j = 0; j < 16; ++j) {
            xxpA[j] = pk2(elu_f(xxA[2 * j]), elu_f(xxA[2 * j + 1]));
            xxpB[j] = pk2(elu_f(xxB[2 * j]), elu_f(xxB[2 * j + 1]));
        }

        // --- vis: t = xx*wn ; hv = elu(vw1.t) ; xx += elu(vb2 + vw2.hv) ; va ---
        const ull wn2A = pk2(wnA, wnA), wn2B = pk2(wnB, wnB);
        ull tpA[16], tpB[16];
        #pragma unroll
        for (int j = 0; j < 16; ++j) { tpA[j] = mul2(xxpA[j], wn2A); tpB[j] = mul2(xxpB[j], wn2B); }

        ull hvpA[16], hvpB[16];
        #pragma unroll
        for (int o = 0; o < 32; o += 2) {
            float pA, pB, qA, qB;
            pdot2<16>(&s_vw1[o * 32],       tpA, tpB, pA, pB);
            pdot2<16>(&s_vw1[(o + 1) * 32], tpA, tpB, qA, qB);
            hvpA[o >> 1] = pk2(elu_f(s_vb1[o] + pA), elu_f(s_vb1[o + 1] + qA));
            hvpB[o >> 1] = pk2(elu_f(s_vb1[o] + pB), elu_f(s_vb1[o + 1] + qB));
        }
        #pragma unroll
        for (int j = 0; j < 32; j += 2) {
            float pA, pB, qA, qB;
            pdot2<16>(&s_vw2[j * 32],       hvpA, hvpB, pA, pB);
            pdot2<16>(&s_vw2[(j + 1) * 32], hvpA, hvpB, qA, qB);
            xxpA[j >> 1] = add2(xxpA[j >> 1], pk2(elu_f(s_vb2[j] + pA), elu_f(s_vb2[j + 1] + qA)));
            xxpB[j >> 1] = add2(xxpB[j >> 1], pk2(elu_f(s_vb2[j] + pB), elu_f(s_vb2[j + 1] + qB)));
        }
        float vaA, vaB;
        pdot2<16>(&s_vw2[32 * 32], hvpA, hvpB, vaA, vaB);
        const float visA = sigm_f(elu_f(s_vb2[32] + vaA)) * mvalA;
        const float visB = sigm_f(elu_f(s_vb2[32] + vaB)) * mvalB;

        // --- vis2: t2 = xx*vis ; s2 = v2b2 + v2w2.elu(v2w1.t2) ---
        const ull vdA = pk2(visA, visA), vdB = pk2(visB, visB);
        #pragma unroll
        for (int j = 0; j < 16; ++j) { tpA[j] = mul2(xxpA[j], vdA); tpB[j] = mul2(xxpB[j], vdB); }

        float s2A = v2b2, s2B = v2b2;
        #pragma unroll
        for (int o = 0; o < 32; o += 2) {
            float pA, pB, qA, qB;
            pdot2<16>(&s_v2w1[o * 32],       tpA, tpB, pA, pB);
            pdot2<16>(&s_v2w1[(o + 1) * 32], tpA, tpB, qA, qB);
            const float w0 = s_v2w2[o], w1 = s_v2w2[o + 1];
            s2A += w0 * elu_f(s_v2b1[o] + pA) + w1 * elu_f(s_v2b1[o + 1] + qA);
            s2B += w0 * elu_f(s_v2b1[o] + pB) + w1 * elu_f(s_v2b1[o + 1] + qB);
        }
        const float vis2A = sigm_f(s2A) * mvalA;
        const float vis2B = sigm_f(s2B) * mvalB;

        Ssum += vis2A + vis2B;
        const ull v2dA = pk2(vis2A, vis2A), v2dB = pk2(vis2B, vis2B);
        #pragma unroll
        for (int j = 0; j < 16; ++j) {
            ull u = s_acc[j * 128 + tid];
            u = fma2(v2dA, xxpA[j], u);
            u = fma2(v2dB, xxpB[j], u);
            s_acc[j * 128 + tid] = u;
            ull w = s_acc[(16 + j) * 128 + tid];
            w = fma2(v2dA, mul2(xxpA[j], xxpA[j]), w);
            w = fma2(v2dB, mul2(xxpB[j], xxpB[j]), w);
            s_acc[(16 + j) * 128 + tid] = w;
        }
    }

    // ================= second mean/var + stat head =================
    const float Sinv  = 1.f / (Ssum + EPS);
    const float w2s   = Ssum * Sinv;
    const float wmean = w2s * 0.125f;

    ull Up[16], Vvp[16];
    {
        const ull sd  = pk2(Sinv, Sinv);
        const float nw = -(2.f - w2s);
        const ull nw2 = pk2(nw, nw);
        #pragma unroll
        for (int j = 0; j < 16; ++j) {
            const ull m2 = mul2(s_acc[j * 128 + tid], sd);
            Up[j]  = m2;
            Vvp[j] = fma2(mul2(m2, m2), nw2, mul2(s_acc[(16 + j) * 128 + tid], sd));
        }
    }

    #pragma unroll 1
    for (int o = 0; o < 32; ++o) {
        const float* wr = &s_sw[o * 68];
        const float acc = s_sb[o] + pdot<16>(wr, Up) + pdot<16>(wr + 32, Vvp) + wr[64] * wmean;
        out[(b * 32 + o) * G3 + v] = elu_f(acc);
    }
}

extern "C" void kernel_launch(void* const* d_in, const int* in_sizes, int n_in,
                              void* d_out, int out_size) {
    (void)in_sizes; (void)n_in; (void)out_size;
    const float* features = (const float*)d_in[0];
    const float* mask     = (const float*)d_in[1];
    const float* depth    = (const float*)d_in[2];
    const float* vdir     = (const float*)d_in[3];
    const float* rde_w1   = (const float*)d_in[4];
    const float* rde_b1   = (const float*)d_in[5];
    const float* rde_w2   = (const float*)d_in[6];
    const float* rde_b2   = (const float*)d_in[7];
    const float* base_w1  = (const float*)d_in[8];
    const float* base_b1  = (const float*)d_in[9];
    const float* base_w2  = (const float*)d_in[10];
    const float* base_b2  = (const float*)d_in[11];
    const float* vis_w1   = (const float*)d_in[12];
    const float* vis_b1   = (const float*)d_in[13];
    const float* vis_w2   = (const float*)d_in[14];
    const float* vis_b2   = (const float*)d_in[15];
    const float* vis2_w1  = (const float*)d_in[16];
    const float* vis2_b1  = (const float*)d_in[17];
    const float* vis2_w2  = (const float*)d_in[18];
    const float* vis2_b2  = (const float*)d_in[19];
    const float* stat_w   = (const float*)d_in[20];
    const float* stat_b   = (const float*)d_in[21];
    float* out = (float*)d_out;

    cudaFuncSetAttribute(ibr_agg_v8_kernel,
                         cudaFuncAttributeMaxDynamicSharedMemorySize, SMEM_BYTES);

    ibr_agg_v8_kernel<<<512, 128, SMEM_BYTES>>>(
        features, mask, depth, vdir,
        rde_w1, rde_b1, rde_w2, rde_b2,
        base_w1, base_b1, base_w2, base_b2,
        vis_w1, vis_b1, vis_w2, vis_b2,
        vis2_w1, vis2_b1, vis2_w2, vis2_b2,
        stat_w, stat_b, out);
}

// round 14
// speedup vs baseline: 1.3237x; 1.0903x over previous
#include <cuda_runtime.h>
#include <math.h>

#define G3 32768
#define NVIEW 8

typedef unsigned long long ull;

__device__ __forceinline__ float elu_f(float x)  { return x > 0.f ? x : (__expf(x) - 1.f); }
__device__ __forceinline__ float sigm_f(float x) { return 1.f / (1.f + __expf(-x)); }

__device__ __forceinline__ ull pk2(float lo, float hi) {
    ull r; asm("mov.b64 %0, {%1, %2};" : "=l"(r) : "f"(lo), "f"(hi)); return r;
}
__device__ __forceinline__ float2 upk2(ull a) {
    float lo, hi; asm("mov.b64 {%0, %1}, %2;" : "=f"(lo), "=f"(hi) : "l"(a));
    return make_float2(lo, hi);
}
__device__ __forceinline__ ull fma2(ull a, ull b, ull c) {
    ull d; asm("fma.rn.f32x2 %0, %1, %2, %3;" : "=l"(d) : "l"(a), "l"(b), "l"(c)); return d;
}
__device__ __forceinline__ ull mul2(ull a, ull b) {
    ull d; asm("mul.rn.f32x2 %0, %1, %2;" : "=l"(d) : "l"(a), "l"(b)); return d;
}
__device__ __forceinline__ ull add2(ull a, ull b) {
    ull d; asm("add.rn.f32x2 %0, %1, %2;" : "=l"(d) : "l"(a), "l"(b)); return d;
}
__device__ __forceinline__ float hsum2(ull a) { float2 f = upk2(a); return f.x + f.y; }

// Packed dot over NP f32x2 pairs with FOUR independent accumulator chains
// (chain depth NP/8 each) — halves the serial fma2 tail vs the 2-chain version.
// NP must be a multiple of 4.
template<int NP>
__device__ __forceinline__ float pdot(const float* __restrict__ wr, const ull* __restrict__ xp) {
    ull a0 = 0ull, a1 = 0ull, a2 = 0ull, a3 = 0ull;
    #pragma unroll
    for (int k = 0; k < NP / 4; ++k) {
        const ulonglong2 w0 = *reinterpret_cast<const ulonglong2*>(wr + 8 * k);
        const ulonglong2 w1 = *reinterpret_cast<const ulonglong2*>(wr + 8 * k + 4);
        a0 = fma2(w0.x, xp[4 * k], a0);
        a1 = fma2(w0.y, xp[4 * k + 1], a1);
        a2 = fma2(w1.x, xp[4 * k + 2], a2);
        a3 = fma2(w1.y, xp[4 * k + 3], a3);
    }
    return hsum2(add2(add2(a0, a1), add2(a2, a3)));
}

__global__ __launch_bounds__(128)
void ibr_agg_v9_kernel(
    const float* __restrict__ features,   // (B,N,32,G3)
    const float* __restrict__ mask,       // (B,N,1,G3)
    const float* __restrict__ depth,      // (B,N,1,G3)
    const float* __restrict__ vdir,       // (B,N,3,G3)
    const float* __restrict__ g_rw1, const float* __restrict__ g_rb1,   // (16,4),(16)
    const float* __restrict__ g_rw2, const float* __restrict__ g_rb2,   // (32,16),(32)
    const float* __restrict__ g_bw1, const float* __restrict__ g_bb1,   // (64,96),(64)
    const float* __restrict__ g_bw2, const float* __restrict__ g_bb2,   // (32,64),(32)
    const float* __restrict__ g_vw1, const float* __restrict__ g_vb1,   // (32,32),(32)
    const float* __restrict__ g_vw2, const float* __restrict__ g_vb2,   // (33,32),(33)
    const float* __restrict__ g_v2w1, const float* __restrict__ g_v2b1, // (32,32),(32)
    const float* __restrict__ g_v2w2, const float* __restrict__ g_v2b2, // (1,32),(1)
    const float* __restrict__ g_sw,  const float* __restrict__ g_sb,    // (32,65),(32)
    float* __restrict__ out)              // (B,32,G3)
{
    __shared__ __align__(16) float s_rw1[16 * 4];
    __shared__ __align__(16) float s_rb1[16];
    __shared__ __align__(16) float s_rw2[32 * 16];
    __shared__ __align__(16) float s_rb2[32];
    __shared__ __align__(16) float s_bw1f[64 * 32];   // base_w1 cols 64..95 (feat part)
    __shared__ __align__(16) float s_bw2[32 * 64];
    __shared__ __align__(16) float s_bb2[32];
    __shared__ __align__(16) float s_vw1[32 * 32];
    __shared__ __align__(16) float s_vb1[32];
    __shared__ __align__(16) float s_vw2[33 * 32];
    __shared__ __align__(16) float s_vb2[36];
    __shared__ __align__(16) float s_v2w1[32 * 32];
    __shared__ __align__(16) float s_v2b1[32];
    __shared__ __align__(16) float s_v2w2[32];
    __shared__ __align__(16) float s_sw[32 * 68];     // stat_w rows padded 65->68
    __shared__ __align__(16) float s_sb[32];

    const int tid = threadIdx.x;

    for (int i = tid; i < 16 * 4;  i += 128) s_rw1[i] = g_rw1[i];
    if (tid < 16) s_rb1[tid] = g_rb1[tid];
    for (int i = tid; i < 32 * 16; i += 128) s_rw2[i] = g_rw2[i];
    if (tid < 32) s_rb2[tid] = g_rb2[tid];
    for (int i = tid; i < 64 * 32; i += 128) { int o = i >> 5, c = i & 31; s_bw1f[i] = g_bw1[o * 96 + 64 + c]; }
    for (int i = tid; i < 32 * 64; i += 128) s_bw2[i] = g_bw2[i];
    if (tid < 32) s_bb2[tid] = g_bb2[tid];
    for (int i = tid; i < 32 * 32; i += 128) s_vw1[i] = g_vw1[i];
    if (tid < 32) s_vb1[tid] = g_vb1[tid];
    for (int i = tid; i < 33 * 32; i += 128) s_vw2[i] = g_vw2[i];
    if (tid < 33) s_vb2[tid] = g_vb2[tid];
    for (int i = tid; i < 32 * 32; i += 128) s_v2w1[i] = g_v2w1[i];
    if (tid < 32) s_v2b1[tid] = g_v2b1[tid];
    if (tid < 32) s_v2w2[tid] = g_v2w2[tid];
    for (int i = tid; i < 32 * 65; i += 128) { int o = i / 65, c = i % 65; s_sw[o * 68 + c] = g_sw[i]; }
    if (tid < 32) s_sb[tid] = g_sb[tid];
    __syncthreads();

    const float EPS  = 1e-8f;
    const float v2b2 = __ldg(g_v2b2);

    const int gv = blockIdx.x * 128 + tid;   // [0, 65536): (b, voxel)
    const int b  = gv >> 15;
    const int v  = gv & (G3 - 1);

    // ---- mask sum ----
    float msum = 0.f;
    #pragma unroll
    for (int n = 0; n < NVIEW; ++n) msum += __ldg(&mask[(b * NVIEW + n) * G3 + v]);
    const float minv = 1.f / (msum + EPS);
    const float ws   = msum * minv;

    // ================= phase 1: packed A1=Sum(w f), A2=Sum(w f^2) =================
    float fsave[NVIEW][32];            // per-thread local cache of feats
    ull A1p[16], A2p[16];
    #pragma unroll
    for (int j = 0; j < 16; ++j) { A1p[j] = 0ull; A2p[j] = 0ull; }

    #pragma unroll 1
    for (int n = 0; n < NVIEW; ++n) {
        const int bn = b * NVIEW + n;
        const float i0 = __ldg(&vdir[(bn * 3 + 0) * G3 + v]);
        const float i1 = __ldg(&vdir[(bn * 3 + 1) * G3 + v]);
        const float i2 = __ldg(&vdir[(bn * 3 + 2) * G3 + v]);
        const float i3 = __ldg(&depth[bn * G3 + v]);
        const float wn = __ldg(&mask[bn * G3 + v]) * minv;
        const ull  wn2 = pk2(wn, wn);

        ull hp8[8];
        #pragma unroll
        for (int o = 0; o < 16; o += 2) {
            const float4 wa = *reinterpret_cast<const float4*>(&s_rw1[o * 4]);
            const float4 wb = *reinterpret_cast<const float4*>(&s_rw1[(o + 1) * 4]);
            const float ha = elu_f(s_rb1[o]     + wa.x * i0 + wa.y * i1 + wa.z * i2 + wa.w * i3);
            const float hb = elu_f(s_rb1[o + 1] + wb.x * i0 + wb.y * i1 + wb.z * i2 + wb.w * i3);
            hp8[o >> 1] = pk2(ha, hb);
        }

        const float* fbase = &features[(bn * 32) * G3 + v];
        #pragma unroll
        for (int j = 0; j < 16; ++j) {
            const float a = __ldg(&fbase[(2 * j) * G3])
                          + elu_f(s_rb2[2 * j] + pdot<8>(&s_rw2[(2 * j) * 16], hp8));
            const float c = __ldg(&fbase[(2 * j + 1) * G3])
                          + elu_f(s_rb2[2 * j + 1] + pdot<8>(&s_rw2[(2 * j + 1) * 16], hp8));
            fsave[n][2 * j]     = a;
            fsave[n][2 * j + 1] = c;
            const ull fp = pk2(a, c);
            A1p[j] = fma2(wn2, fp, A1p[j]);
            A2p[j] = fma2(wn2, mul2(fp, fp), A2p[j]);
        }
    }

    // mean/var packed: var = A2 - mean^2 (2 - ws)
    {
        const float nw = -(2.f - ws);
        const ull  nw2 = pk2(nw, nw);
        #pragma unroll
        for (int j = 0; j < 16; ++j) {
            const ull m = A1p[j];
            A2p[j] = fma2(mul2(m, m), nw2, A2p[j]);   // A1p = mean, A2p = var
        }
    }

    // ---- hbase[o] = bb1[o] + bw1[o,0:32].mean + bw1[o,32:64].var (local) ----
    float hbase[64];
    #pragma unroll 1
    for (int o = 0; o < 64; ++o) {
        const float* rm = &g_bw1[o * 96];
        hbase[o] = __ldg(&g_bb1[o]) + pdot<16>(rm, A1p) + pdot<16>(rm + 32, A2p);
    }

    // ================= phase 2: per-view MLPs; S, Up, Vvp =================
    ull Up[16], Vvp[16];
    float S = 0.f;
    #pragma unroll
    for (int j = 0; j < 16; ++j) { Up[j] = 0ull; Vvp[j] = 0ull; }

    #pragma unroll 1
    for (int n = 0; n < NVIEW; ++n) {
        const int bn = b * NVIEW + n;
        const float mval = __ldg(&mask[bn * G3 + v]);
        const float wn   = mval * minv;

        ull fp[16];
        #pragma unroll
        for (int j = 0; j < 16; ++j) fp[j] = pk2(fsave[n][2 * j], fsave[n][2 * j + 1]);

        // --- base: h = elu(hbase + bw1f.f) (64); xx = elu(bb2 + bw2.h) (32); 16-chunks ---
        float xx[32];
        #pragma unroll
        for (int j = 0; j < 32; ++j) xx[j] = s_bb2[j];

        #pragma unroll 1
        for (int oc = 0; oc < 4; ++oc) {
            const int o16 = oc * 16;
            ull hp[8];
            #pragma unroll
            for (int k = 0; k < 16; k += 2) {
                const float ha = elu_f(hbase[o16 + k]     + pdot<16>(&s_bw1f[(o16 + k) * 32], fp));
                const float hb = elu_f(hbase[o16 + k + 1] + pdot<16>(&s_bw1f[(o16 + k + 1) * 32], fp));
                hp[k >> 1] = pk2(ha, hb);
            }
            #pragma unroll
            for (int j = 0; j < 32; ++j)
                xx[j] += pdot<8>(&s_bw2[j * 64 + o16], hp);
        }
        ull xxp[16];
        #pragma unroll
        for (int j = 0; j < 16; ++j)
            xxp[j] = pk2(elu_f(xx[2 * j]), elu_f(xx[2 * j + 1]));

        // --- vis: t = xx*wn ; hv = elu(vw1.t) ; xx += elu(vb2 + vw2.hv) ; va ---
        const ull wn2 = pk2(wn, wn);
        ull tp[16];
        #pragma unroll
        for (int j = 0; j < 16; ++j) tp[j] = mul2(xxp[j], wn2);

        ull hvp[16];
        #pragma unroll
        for (int o = 0; o < 32; o += 2) {
            const float a = elu_f(s_vb1[o]     + pdot<16>(&s_vw1[o * 32], tp));
            const float c = elu_f(s_vb1[o + 1] + pdot<16>(&s_vw1[(o + 1) * 32], tp));
            hvp[o >> 1] = pk2(a, c);
        }
        #pragma unroll
        for (int j = 0; j < 32; j += 2) {
            const float a = elu_f(s_vb2[j]     + pdot<16>(&s_vw2[j * 32], hvp));
            const float c = elu_f(s_vb2[j + 1] + pdot<16>(&s_vw2[(j + 1) * 32], hvp));
            xxp[j >> 1] = add2(xxp[j >> 1], pk2(a, c));       // x = x + x_res
        }
        const float va  = s_vb2[32] + pdot<16>(&s_vw2[32 * 32], hvp);
        const float vis = sigm_f(elu_f(va)) * mval;

        // --- vis2: t2 = xx*vis ; s2 = v2b2 + v2w2.elu(v2w1.t2) ---
        const ull visd = pk2(vis, vis);
        #pragma unroll
        for (int j = 0; j < 16; ++j) tp[j] = mul2(xxp[j], visd);

        float s2 = v2b2;
        #pragma unroll
        for (int o = 0; o < 32; o += 2) {
            const float a = elu_f(s_v2b1[o]     + pdot<16>(&s_v2w1[o * 32], tp));
            const float c = elu_f(s_v2b1[o + 1] + pdot<16>(&s_v2w1[(o + 1) * 32], tp));
            s2 += s_v2w2[o] * a + s_v2w2[o + 1] * c;
        }
        const float vis2 = sigm_f(s2) * mval;

        S += vis2;
        const ull v2d = pk2(vis2, vis2);
        #pragma unroll
        for (int j = 0; j < 16; ++j) {
            Up[j]  = fma2(v2d, xxp[j], Up[j]);
            Vvp[j] = fma2(v2d, mul2(xxp[j], xxp[j]), Vvp[j]);
        }
    }

    // ================= second mean/var + stat head (packed) =================
    const float Sinv  = 1.f / (S + EPS);
    const float w2s   = S * Sinv;
    const float wmean = w2s * 0.125f;
    {
        const ull sd  = pk2(Sinv, Sinv);
        const float nw = -(2.f - w2s);
        const ull nw2 = pk2(nw, nw);
        #pragma unroll
        for (int j = 0; j < 16; ++j) {
            const ull m2 = mul2(Up[j], sd);
            Up[j]  = m2;                                        // mean2
            Vvp[j] = fma2(mul2(m2, m2), nw2, mul2(Vvp[j], sd)); // var2
        }
    }

    #pragma unroll 1
    for (int o = 0; o < 32; ++o) {
        const float* wr = &s_sw[o * 68];
        const float acc = s_sb[o] + pdot<16>(wr, Up) + pdot<16>(wr + 32, Vvp) + wr[64] * wmean;
        out[(b * 32 + o) * G3 + v] = elu_f(acc);
    }
}

extern "C" void kernel_launch(void* const* d_in, const int* in_sizes, int n_in,
                              void* d_out, int out_size) {
    (void)in_sizes; (void)n_in; (void)out_size;
    const float* features = (const float*)d_in[0];
    const float* mask     = (const float*)d_in[1];
    const float* depth    = (const float*)d_in[2];
    const float* vdir     = (const float*)d_in[3];
    const float* rde_w1   = (const float*)d_in[4];
    const float* rde_b1   = (const float*)d_in[5];
    const float* rde_w2   = (const float*)d_in[6];
    const float* rde_b2   = (const float*)d_in[7];
    const float* base_w1  = (const float*)d_in[8];
    const float* base_b1  = (const float*)d_in[9];
    const float* base_w2  = (const float*)d_in[10];
    const float* base_b2  = (const float*)d_in[11];
    const float* vis_w1   = (const float*)d_in[12];
    const float* vis_b1   = (const float*)d_in[13];
    const float* vis_w2   = (const float*)d_in[14];
    const float* vis_b2   = (const float*)d_in[15];
    const float* vis2_w1  = (const float*)d_in[16];
    const float* vis2_b1  = (const float*)d_in[17];
    const float* vis2_w2  = (const float*)d_in[18];
    const float* vis2_b2  = (const float*)d_in[19];
    const float* stat_w   = (const float*)d_in[20];
    const float* stat_b   = (const float*)d_in[21];
    float* out = (float*)d_out;

    ibr_agg_v9_kernel<<<512, 128>>>(
        features, mask, depth, vdir,
        rde_w1, rde_b1, rde_w2, rde_b2,
        base_w1, base_b1, base_w2, base_b2,
        vis_w1, vis_b1, vis_w2, vis_b2,
        vis2_w1, vis2_b1, vis2_w2, vis2_b2,
        stat_w, stat_b, out);
}